// round 3
// baseline (speedup 1.0000x reference)
#include <cuda_runtime.h>
#include <cuda_bf16.h>

#define NN 50000
#define EE 800000
#define D 96
#define ED 32

// ---------------- static device scratch (16B-aligned, no allocations) ----------------
__device__ __align__(16) int   g_deg[NN];
__device__ __align__(16) int   g_rowptr[NN + 1];
__device__ __align__(16) int   g_fill[NN];
__device__ __align__(16) int   g_eidx[EE];
__device__ __align__(16) float g_h [NN * D];   // x + aggr
__device__ __align__(16) float g_h1[NN * D];   // relu(h @ W1 + b1)
__device__ __align__(16) float g_h2[NN * D];   // h1 @ W2 + b2
__device__ __align__(16) float g_sum[D];
__device__ __align__(16) float g_sumsq[D];
__device__ int g_is64;

// index accessor: logical layout (2, EE); pos in [0, 2*EE)
__device__ __forceinline__ int load_idx(const void* ei, int pos) {
    if (g_is64) return (int)((const long long*)ei)[pos];
    return ((const int*)ei)[pos];
}

// ---------------- dtype detection ----------------
__global__ void k_detect(const unsigned int* __restrict__ w) {
    if (threadIdx.x == 0 && blockIdx.x == 0) {
        int is64 = 1;
        for (int i = 0; i < 64; i++)
            if (w[2 * i + 1] != 0u) { is64 = 0; break; }
        g_is64 = is64;
    }
}

// ---------------- CSR build ----------------
__global__ void k_zero() {
    int i = blockIdx.x * blockDim.x + threadIdx.x;
    if (i < NN) g_deg[i] = 0;
    if (i < D) { g_sum[i] = 0.f; g_sumsq[i] = 0.f; }
}

__global__ void k_count(const void* __restrict__ ei) {
    int e = blockIdx.x * blockDim.x + threadIdx.x;
    if (e < EE) {
        int dst = load_idx(ei, EE + e);
        if ((unsigned)dst < (unsigned)NN) atomicAdd(&g_deg[dst], 1);
    }
}

__global__ void k_scan() {
    __shared__ int part[1024];
    int t = threadIdx.x;
    const int C = (NN + 1023) / 1024;           // 49
    int lo = t * C;
    int hi = lo + C; if (hi > NN) hi = NN; if (lo > NN) lo = NN;
    int s = 0;
    for (int i = lo; i < hi; i++) s += g_deg[i];
    part[t] = s;
    __syncthreads();
    for (int off = 1; off < 1024; off <<= 1) {
        int u = (t >= off) ? part[t - off] : 0;
        __syncthreads();
        part[t] += u;
        __syncthreads();
    }
    int run = (t == 0) ? 0 : part[t - 1];
    for (int i = lo; i < hi; i++) {
        g_rowptr[i] = run;
        g_fill[i]   = run;
        run += g_deg[i];
    }
    if (t == 1023) g_rowptr[NN] = part[1023];
}

__global__ void k_fill(const void* __restrict__ ei) {
    int e = blockIdx.x * blockDim.x + threadIdx.x;
    if (e < EE) {
        int dst = load_idx(ei, EE + e);
        if ((unsigned)dst < (unsigned)NN) {
            int pos = atomicAdd(&g_fill[dst], 1);
            if ((unsigned)pos < (unsigned)EE) g_eidx[pos] = e;
        }
    }
}

// ---------------- edge message + pull aggregation (warp per node) ----------------
__global__ void __launch_bounds__(256) k_gather(
    const float* __restrict__ x, const void* __restrict__ ei,
    const float* __restrict__ ea, const float* __restrict__ We,
    const float* __restrict__ be)
{
    int warp = (blockIdx.x * blockDim.x + threadIdx.x) >> 5;
    int lane = threadIdx.x & 31;
    if (warp >= NN) return;               // warp-uniform exit

    // register-resident We columns for this lane's 3 output dims
    float w0[ED], w1[ED], w2[ED];
#pragma unroll
    for (int k = 0; k < ED; k++) {
        w0[k] = We[k * D + lane];
        w1[k] = We[k * D + lane + 32];
        w2[k] = We[k * D + lane + 64];
    }
    float be0 = be[lane], be1 = be[lane + 32], be2 = be[lane + 64];

    int node = warp;
    int beg = g_rowptr[node], end = g_rowptr[node + 1];
    float a0 = 0.f, a1 = 0.f, a2 = 0.f;
    for (int j = beg; j < end; j++) {
        int e = g_eidx[j];
        int src = load_idx(ei, e);
        if ((unsigned)src >= (unsigned)NN) continue;
        float eav = ea[(long long)e * ED + lane];
        float p0 = be0, p1 = be1, p2 = be2;
#pragma unroll
        for (int k = 0; k < ED; k++) {
            float b = __shfl_sync(0xffffffffu, eav, k);
            p0 += b * w0[k];
            p1 += b * w1[k];
            p2 += b * w2[k];
        }
        const float* xs = x + (long long)src * D;
        a0 += fmaxf(xs[lane]      + p0, 0.f);
        a1 += fmaxf(xs[lane + 32] + p1, 0.f);
        a2 += fmaxf(xs[lane + 64] + p2, 0.f);
    }
    const float* xn = x + (long long)node * D;
    g_h[node * D + lane]      = xn[lane]      + a0;
    g_h[node * D + lane + 32] = xn[lane + 32] + a1;
    g_h[node * D + lane + 64] = xn[lane + 64] + a2;
}

// ---------------- dense layer: stage 0: g_h -> g_h1 (ReLU); stage 1: g_h1 -> g_h2 (+stats) ----------------
__global__ void __launch_bounds__(128) k_mlp(
    const float* __restrict__ W, const float* __restrict__ bias, int stage)
{
    __shared__ __align__(16) float Ws[32 * D];       // 12 KB
    __shared__ __align__(16) float hs[128 * 33];     // 16.5 KB, padded

    const float* hin  = (stage == 0) ? g_h  : g_h1;
    float*       hout = (stage == 0) ? g_h1 : g_h2;

    int tid  = threadIdx.x;
    int base = blockIdx.x * 128;
    int node = base + tid;
    bool valid = node < NN;

    float acc[D];
#pragma unroll
    for (int j = 0; j < D; j++) acc[j] = bias[j];

    for (int kt = 0; kt < 3; kt++) {
        for (int i = tid; i < 32 * D; i += 128) Ws[i] = W[kt * 32 * D + i];
        for (int i = tid; i < 128 * 32; i += 128) {
            int r = i >> 5, kk = i & 31;
            int nd = base + r;
            hs[r * 33 + kk] = (nd < NN) ? hin[(long long)nd * D + kt * 32 + kk] : 0.f;
        }
        __syncthreads();

#pragma unroll 8
        for (int kk = 0; kk < 32; kk++) {
            float hk = hs[tid * 33 + kk];
            const float4* w4 = (const float4*)(Ws + kk * D);
#pragma unroll
            for (int j4 = 0; j4 < D / 4; j4++) {
                float4 w = w4[j4];
                acc[4 * j4 + 0] += hk * w.x;
                acc[4 * j4 + 1] += hk * w.y;
                acc[4 * j4 + 2] += hk * w.z;
                acc[4 * j4 + 3] += hk * w.w;
            }
        }
        __syncthreads();
    }

    if (stage == 0) {
#pragma unroll
        for (int j = 0; j < D; j++) acc[j] = fmaxf(acc[j], 0.f);
    }
    if (valid) {
        float4* out4 = (float4*)(hout + (long long)node * D);
#pragma unroll
        for (int j4 = 0; j4 < D / 4; j4++)
            out4[j4] = make_float4(acc[4 * j4], acc[4 * j4 + 1],
                                   acc[4 * j4 + 2], acc[4 * j4 + 3]);
    }
    if (stage == 1) {
#pragma unroll
        for (int j = 0; j < D; j++) {
            float v  = valid ? acc[j] : 0.f;
            float s2 = v * v;
            for (int off = 16; off; off >>= 1) {
                v  += __shfl_down_sync(0xffffffffu, v,  off);
                s2 += __shfl_down_sync(0xffffffffu, s2, off);
            }
            if ((tid & 31) == 0) {
                atomicAdd(&g_sum[j],   v);
                atomicAdd(&g_sumsq[j], s2);
            }
        }
    }
}

// ---------------- batchnorm + relu ----------------
__global__ void k_bn(const float* __restrict__ gamma,
                     const float* __restrict__ beta,
                     float* __restrict__ out)
{
    int i = blockIdx.x * blockDim.x + threadIdx.x;   // float4 index
    const int TOT4 = NN * D / 4;
    if (i >= TOT4) return;
    int c = (i * 4) % D;
    const float invN = 1.0f / (float)NN;
    float4 h = ((const float4*)g_h2)[i];
    float hv[4] = {h.x, h.y, h.z, h.w};
    float o[4];
#pragma unroll
    for (int u = 0; u < 4; u++) {
        int cc = c + u;
        float mean = g_sum[cc] * invN;
        float var  = g_sumsq[cc] * invN - mean * mean;
        float inv  = rsqrtf(var + 1e-5f);
        o[u] = fmaxf((hv[u] - mean) * inv * gamma[cc] + beta[cc], 0.f);
    }
    ((float4*)out)[i] = make_float4(o[0], o[1], o[2], o[3]);
}

// ---------------- launch (launches only: graph-capturable, no statics) ----------------
extern "C" void kernel_launch(void* const* d_in, const int* in_sizes, int n_in,
                              void* d_out, int out_size)
{
    const float* x     = (const float*)d_in[0];
    const void*  ei    = d_in[1];
    const float* ea    = (const float*)d_in[2];
    const float* We    = (const float*)d_in[3];
    const float* be    = (const float*)d_in[4];
    const float* W1    = (const float*)d_in[5];
    const float* b1    = (const float*)d_in[6];
    const float* W2    = (const float*)d_in[7];
    const float* b2    = (const float*)d_in[8];
    const float* gamma = (const float*)d_in[9];
    const float* beta  = (const float*)d_in[10];
    float*       out   = (float*)d_out;

    k_detect<<<1, 32>>>((const unsigned int*)ei);
    k_zero  <<<(NN + 255) / 256, 256>>>();
    k_count <<<(EE + 255) / 256, 256>>>(ei);
    k_scan  <<<1, 1024>>>();
    k_fill  <<<(EE + 255) / 256, 256>>>(ei);
    k_gather<<<NN / 8, 256>>>(x, ei, ea, We, be);   // 6250 blocks * 8 warps = 50000 warps
    k_mlp   <<<(NN + 127) / 128, 128>>>(W1, b1, 0);
    k_mlp   <<<(NN + 127) / 128, 128>>>(W2, b2, 1);
    k_bn    <<<(NN * D / 4 + 255) / 256, 256>>>(gamma, beta, out);
}

// round 4
// speedup vs baseline: 1.2082x; 1.2082x over previous
#include <cuda_runtime.h>
#include <cuda_bf16.h>

#define NN 50000
#define EE 800000
#define D 96
#define ED 32
#define NB 391   // ceil(NN/128)

typedef unsigned long long ull;

#define PACK2(d, lo, hi)  asm("mov.b64 %0, {%1, %2};" : "=l"(d) : "f"(lo), "f"(hi))
#define UNPACK2(lo, hi, s) asm("mov.b64 {%0, %1}, %2;" : "=f"(lo), "=f"(hi) : "l"(s))
#define FMA2(d, a, b, c)  asm("fma.rn.f32x2 %0, %1, %2, %3;" : "=l"(d) : "l"(a), "l"(b), "l"(c))

// ---------------- static device scratch ----------------
__device__ __align__(16) int   g_deg[NN];
__device__ __align__(16) int   g_part[512];
__device__ __align__(16) int   g_rowptr[NN + 1];
__device__ __align__(16) int   g_fill[NN];
__device__ __align__(16) int   g_eidx[EE];
__device__ __align__(16) float g_proj[(long long)EE * D];  // edge projections (307 MB)
__device__ __align__(16) float g_h [NN * D];
__device__ __align__(16) float g_h1[NN * D];
__device__ __align__(16) float g_h2[NN * D];
__device__ __align__(16) float g_sum[D];
__device__ __align__(16) float g_sumsq[D];
__device__ int g_is64;

__device__ __forceinline__ int load_idx(const void* ei, int pos) {
    if (g_is64) return (int)((const long long*)ei)[pos];
    return ((const int*)ei)[pos];
}
__device__ __forceinline__ int clampN(int v, int n) {
    return v < 0 ? 0 : (v >= n ? n - 1 : v);
}

// ---------------- dtype detection (1 warp, parallel) ----------------
__global__ void k_detect(const unsigned int* __restrict__ w) {
    int t = threadIdx.x;
    unsigned v = w[2 * t + 1];                 // high words of first 32 values if int64
    unsigned b = __ballot_sync(0xffffffffu, v != 0u);
    if (t == 0) g_is64 = (b == 0u) ? 1 : 0;
}

// ---------------- CSR build ----------------
__global__ void k_zero() {
    int i = blockIdx.x * blockDim.x + threadIdx.x;
    if (i < NN) g_deg[i] = 0;
    if (i < D) { g_sum[i] = 0.f; g_sumsq[i] = 0.f; }
}

__global__ void k_count(const void* __restrict__ ei) {
    int e = blockIdx.x * blockDim.x + threadIdx.x;
    if (e < EE) {
        int dst = load_idx(ei, EE + e);
        if ((unsigned)dst < (unsigned)NN) atomicAdd(&g_deg[dst], 1);
    }
}

__global__ void k_scan1() {                   // NB blocks x 128: block sums
    __shared__ int s[128];
    int t = threadIdx.x;
    int i = blockIdx.x * 128 + t;
    s[t] = (i < NN) ? g_deg[i] : 0;
    __syncthreads();
    for (int off = 64; off; off >>= 1) {
        if (t < off) s[t] += s[t + off];
        __syncthreads();
    }
    if (t == 0) g_part[blockIdx.x] = s[0];
}

__global__ void k_scan2() {                   // 1 block x 512: inclusive scan of partials
    __shared__ int s[512];
    int t = threadIdx.x;
    s[t] = (t < NB) ? g_part[t] : 0;
    __syncthreads();
    for (int off = 1; off < 512; off <<= 1) {
        int u = (t >= off) ? s[t - off] : 0;
        __syncthreads();
        s[t] += u;
        __syncthreads();
    }
    if (t < NB) g_part[t] = s[t];
}

__global__ void k_scan3() {                   // NB blocks x 128: exclusive offsets
    __shared__ int s[128];
    int t = threadIdx.x;
    int i = blockIdx.x * 128 + t;
    int v = (i < NN) ? g_deg[i] : 0;
    s[t] = v;
    __syncthreads();
    for (int off = 1; off < 128; off <<= 1) {
        int u = (t >= off) ? s[t - off] : 0;
        __syncthreads();
        s[t] += u;
        __syncthreads();
    }
    int base = blockIdx.x ? g_part[blockIdx.x - 1] : 0;
    if (i < NN) {
        int ex = base + s[t] - v;
        g_rowptr[i] = ex;
        g_fill[i]   = ex;
        if (i == NN - 1) g_rowptr[NN] = base + s[t];
    }
}

__global__ void k_fill(const void* __restrict__ ei) {
    int e = blockIdx.x * blockDim.x + threadIdx.x;
    if (e < EE) {
        int dst = load_idx(ei, EE + e);
        if ((unsigned)dst < (unsigned)NN) {
            int pos = atomicAdd(&g_fill[dst], 1);
            if ((unsigned)pos < (unsigned)EE) g_eidx[pos] = e;
        }
    }
}

// ---------------- Phase A: edge projection GEMM (thread per edge, FFMA2) ----------------
__global__ void __launch_bounds__(256) k_edgemsg(
    const float* __restrict__ ea, const float* __restrict__ We,
    const float* __restrict__ be)
{
    __shared__ __align__(16) float We_s[ED * D];     // 12 KB
    __shared__ __align__(16) float ea_s[256 * 33];   // 33.8 KB, padded
    __shared__ __align__(16) float be_s[D];

    int tid = threadIdx.x;
    long long e0 = (long long)blockIdx.x * 256;

    for (int i = tid; i < ED * D; i += 256) We_s[i] = We[i];
    if (tid < D) be_s[tid] = be[tid];
    for (int i = tid; i < 256 * ED; i += 256) {
        int r = i >> 5, c = i & 31;
        ea_s[r * 33 + c] = ea[(e0 + r) * ED + c];
    }
    __syncthreads();

    ull acc[48];
#pragma unroll
    for (int j = 0; j < 48; j++) PACK2(acc[j], be_s[2 * j], be_s[2 * j + 1]);

#pragma unroll 2
    for (int k = 0; k < ED; k++) {
        float hk = ea_s[tid * 33 + k];
        ull hk2; PACK2(hk2, hk, hk);
        const ulonglong2* w2 = (const ulonglong2*)(We_s + k * D);
#pragma unroll
        for (int j = 0; j < 24; j++) {
            ulonglong2 w = w2[j];
            FMA2(acc[2 * j],     hk2, w.x, acc[2 * j]);
            FMA2(acc[2 * j + 1], hk2, w.y, acc[2 * j + 1]);
        }
    }

    ull* out = (ull*)(g_proj + (e0 + tid) * D);
#pragma unroll
    for (int j = 0; j < 48; j++) out[j] = acc[j];
}

// ---------------- Phase B: pull aggregation (warp per node) ----------------
__global__ void __launch_bounds__(256) k_aggr(
    const float* __restrict__ x, const void* __restrict__ ei)
{
    int warp = (blockIdx.x * blockDim.x + threadIdx.x) >> 5;
    int lane = threadIdx.x & 31;
    if (warp >= NN) return;

    int node = warp;
    int beg = g_rowptr[node], end = g_rowptr[node + 1];
    float a0 = 0.f, a1 = 0.f, a2 = 0.f;
    for (int j = beg; j < end; j++) {
        int e = clampN(g_eidx[j], EE);
        int src = clampN(load_idx(ei, e), NN);
        const float* pr = g_proj + (long long)e * D;
        const float* xs = x + (long long)src * D;
        a0 += fmaxf(xs[lane]      + pr[lane],      0.f);
        a1 += fmaxf(xs[lane + 32] + pr[lane + 32], 0.f);
        a2 += fmaxf(xs[lane + 64] + pr[lane + 64], 0.f);
    }
    const float* xn = x + (long long)node * D;
    g_h[node * D + lane]      = xn[lane]      + a0;
    g_h[node * D + lane + 32] = xn[lane + 32] + a1;
    g_h[node * D + lane + 64] = xn[lane + 64] + a2;
}

// ---------------- dense layer (FFMA2): stage 0: g_h->g_h1 (ReLU); stage 1: g_h1->g_h2 (+stats) ----------------
__global__ void __launch_bounds__(128) k_mlp(
    const float* __restrict__ W, const float* __restrict__ bias, int stage)
{
    __shared__ __align__(16) float Ws[32 * D];       // 12 KB
    __shared__ __align__(16) float hs[128 * 33];     // 16.5 KB

    const float* hin  = (stage == 0) ? g_h  : g_h1;
    float*       hout = (stage == 0) ? g_h1 : g_h2;

    int tid  = threadIdx.x;
    int base = blockIdx.x * 128;
    int node = base + tid;
    bool valid = node < NN;

    ull acc[48];
#pragma unroll
    for (int j = 0; j < 48; j++) { float b0 = bias[2 * j], b1 = bias[2 * j + 1]; PACK2(acc[j], b0, b1); }

    for (int kt = 0; kt < 3; kt++) {
        for (int i = tid; i < 32 * D; i += 128) Ws[i] = W[kt * 32 * D + i];
        for (int i = tid; i < 128 * 32; i += 128) {
            int r = i >> 5, kk = i & 31;
            int nd = base + r;
            hs[r * 33 + kk] = (nd < NN) ? hin[(long long)nd * D + kt * 32 + kk] : 0.f;
        }
        __syncthreads();

#pragma unroll 2
        for (int kk = 0; kk < 32; kk++) {
            float hk = hs[tid * 33 + kk];
            ull hk2; PACK2(hk2, hk, hk);
            const ulonglong2* w2 = (const ulonglong2*)(Ws + kk * D);
#pragma unroll
            for (int j = 0; j < 24; j++) {
                ulonglong2 w = w2[j];
                FMA2(acc[2 * j],     hk2, w.x, acc[2 * j]);
                FMA2(acc[2 * j + 1], hk2, w.y, acc[2 * j + 1]);
            }
        }
        __syncthreads();
    }

    float v[D];
#pragma unroll
    for (int j = 0; j < 48; j++) UNPACK2(v[2 * j], v[2 * j + 1], acc[j]);

    if (stage == 0) {
#pragma unroll
        for (int j = 0; j < D; j++) v[j] = fmaxf(v[j], 0.f);
    }
    if (valid) {
        float4* out4 = (float4*)(hout + (long long)node * D);
#pragma unroll
        for (int j4 = 0; j4 < D / 4; j4++)
            out4[j4] = make_float4(v[4 * j4], v[4 * j4 + 1], v[4 * j4 + 2], v[4 * j4 + 3]);
    }
    if (stage == 1) {
#pragma unroll
        for (int j = 0; j < D; j++) {
            float s1 = valid ? v[j] : 0.f;
            float s2 = s1 * s1;
            for (int off = 16; off; off >>= 1) {
                s1 += __shfl_down_sync(0xffffffffu, s1, off);
                s2 += __shfl_down_sync(0xffffffffu, s2, off);
            }
            if ((tid & 31) == 0) {
                atomicAdd(&g_sum[j],   s1);
                atomicAdd(&g_sumsq[j], s2);
            }
        }
    }
}

// ---------------- batchnorm + relu ----------------
__global__ void k_bn(const float* __restrict__ gamma,
                     const float* __restrict__ beta,
                     float* __restrict__ out)
{
    int i = blockIdx.x * blockDim.x + threadIdx.x;   // float4 index
    const int TOT4 = NN * D / 4;
    if (i >= TOT4) return;
    int c = (i * 4) % D;
    const float invN = 1.0f / (float)NN;
    float4 h = ((const float4*)g_h2)[i];
    float hv[4] = {h.x, h.y, h.z, h.w};
    float o[4];
#pragma unroll
    for (int u = 0; u < 4; u++) {
        int cc = c + u;
        float mean = g_sum[cc] * invN;
        float var  = g_sumsq[cc] * invN - mean * mean;
        float inv  = rsqrtf(var + 1e-5f);
        o[u] = fmaxf((hv[u] - mean) * inv * gamma[cc] + beta[cc], 0.f);
    }
    ((float4*)out)[i] = make_float4(o[0], o[1], o[2], o[3]);
}

// ---------------- launch ----------------
extern "C" void kernel_launch(void* const* d_in, const int* in_sizes, int n_in,
                              void* d_out, int out_size)
{
    const float* x     = (const float*)d_in[0];
    const void*  ei    = d_in[1];
    const float* ea    = (const float*)d_in[2];
    const float* We    = (const float*)d_in[3];
    const float* be    = (const float*)d_in[4];
    const float* W1    = (const float*)d_in[5];
    const float* b1    = (const float*)d_in[6];
    const float* W2    = (const float*)d_in[7];
    const float* b2    = (const float*)d_in[8];
    const float* gamma = (const float*)d_in[9];
    const float* beta  = (const float*)d_in[10];
    float*       out   = (float*)d_out;

    k_detect <<<1, 32>>>((const unsigned int*)ei);
    k_zero   <<<(NN + 255) / 256, 256>>>();
    k_count  <<<(EE + 255) / 256, 256>>>(ei);
    k_scan1  <<<NB, 128>>>();
    k_scan2  <<<1, 512>>>();
    k_scan3  <<<NB, 128>>>();
    k_fill   <<<(EE + 255) / 256, 256>>>(ei);
    k_edgemsg<<<EE / 256, 256>>>(ea, We, be);
    k_aggr   <<<NN / 8, 256>>>(x, ei);
    k_mlp    <<<(NN + 127) / 128, 128>>>(W1, b1, 0);
    k_mlp    <<<(NN + 127) / 128, 128>>>(W2, b2, 1);
    k_bn     <<<(NN * D / 4 + 255) / 256, 256>>>(gamma, beta, out);
}